// round 15
// baseline (speedup 1.0000x reference)
#include <cuda_runtime.h>
#include <math.h>
#include <stdint.h>

// dims
#define Bn   32
#define Sn   512
#define In   256
#define Hn   512
#define G4n  2048
#define En   1024
#define NPACK 2176   // 1024 K-rows + 1024 V-rows + 64 Q15-rows + 64 zero pad
#define NGRP 4       // batch groups (8 batches each), 32 blocks per group

typedef unsigned long long ull;

// ---------------- static device scratch ----------------
__device__ float d_xg [(size_t)Sn * Bn * G4n];   // fwd input gates, row m=s*32+b, col g (128 MB)
__device__ float d_xgb[(size_t)16 * Bn * G4n];   // bwd input gates, row m=srel*32+b
__device__ ull   d_hring[Sn][NGRP][Hn][8];       // h per step, duplicated f32x2 (64 MB ring)
__device__ float d_hsel[(size_t)Bn * 16 * En];   // h at s in [496,512): [(b*16+srel)][e]
__device__ float d_wpack[(size_t)NPACK * En];
__device__ float d_bpack[NPACK];
__device__ float d_att[(size_t)512 * NPACK];     // per (b,srel): K(1024) V(1024) Q15(64)
__device__ float d_weff[En];
__device__ float d_scal0;

// per-producer flags: one 128B L2 line each. flag = number of completed steps.
struct __align__(128) BarLine { unsigned v; unsigned pad[31]; };
__device__ BarLine d_flag[2][NGRP][32];          // [dircol][group][producer blk]

__device__ __forceinline__ float sigf(float x) { return 1.0f / (1.0f + expf(-x)); }

__device__ __forceinline__ unsigned ld_acq(const unsigned* p) {
    unsigned v;
    asm volatile("ld.acquire.gpu.u32 %0, [%1];" : "=r"(v) : "l"(p) : "memory");
    return v;
}
__device__ __forceinline__ void st_rel(unsigned* p, unsigned v) {
    asm volatile("st.release.gpu.u32 [%0], %1;" :: "l"(p), "r"(v) : "memory");
}

// ---- packed fp32x2 helpers (bit-exact 2x fp32 FMA) ----
__device__ __forceinline__ ull ffma2(ull a, ull b, ull c) {
    ull d;
    asm("fma.rn.f32x2 %0, %1, %2, %3;" : "=l"(d) : "l"(a), "l"(b), "l"(c));
    return d;
}
__device__ __forceinline__ ull pk2(float x, float y) {
    ull r;
    asm("mov.b64 %0, {%1, %2};" : "=l"(r)
        : "r"(__float_as_uint(x)), "r"(__float_as_uint(y)));
    return r;
}
__device__ __forceinline__ void upk2(ull v, float& x, float& y) {
    unsigned lo, hi;
    asm("mov.b64 {%0, %1}, %2;" : "=r"(lo), "=r"(hi) : "l"(v));
    x = __uint_as_float(lo); y = __uint_as_float(hi);
}

// ======================= K0: re-arm flags (each replay) ====================
__global__ void k_flagreset()
{
    BarLine* f = &d_flag[0][0][0];
    f[threadIdx.x].v = 0u;    // 256 = 2*4*32
}

// ======================= K1: xg = x @ W_ih^T + b ===========================
__global__ void __launch_bounds__(256) k_xg(
    const float* __restrict__ x,
    const float* __restrict__ Wihf, const float* __restrict__ bf,
    const float* __restrict__ Wihb, const float* __restrict__ bb)
{
    __shared__ __align__(16) float A_sm[8][128];
    __shared__ __align__(16) float B_sm[8][128];
    const int tid = threadIdx.x;
    const bool bwd = (blockIdx.y >= 128);
    const float* __restrict__ W    = bwd ? Wihb : Wihf;
    const float* __restrict__ bias = bwd ? bb   : bf;
    const int m0 = blockIdx.y * 128;
    const int n0 = blockIdx.x * 128;

    const int lrow = tid >> 1;
    const int lk   = (tid & 1) * 4;
    const int mg = m0 + lrow;
    int sA, bA;
    if (!bwd) { sA = mg >> 5; bA = mg & 31; }
    else { const int ml = mg - 16384; sA = 496 + (ml >> 5); bA = ml & 31; }
    const float* __restrict__ xrow = x + ((size_t)bA * Sn + sA) * In;
    const float* __restrict__ wrow = W + (size_t)(n0 + lrow) * In;

    const int tm = tid >> 4;
    const int tn = tid & 15;

    ull acc[8][4];
#pragma unroll
    for (int i = 0; i < 8; ++i)
#pragma unroll
        for (int p = 0; p < 4; ++p) acc[i][p] = 0ull;

    for (int k0 = 0; k0 < In; k0 += 8) {
        float4 av = *(const float4*)(xrow + k0 + lk);
        float4 bv = *(const float4*)(wrow + k0 + lk);
        __syncthreads();
        A_sm[lk + 0][lrow] = av.x; A_sm[lk + 1][lrow] = av.y;
        A_sm[lk + 2][lrow] = av.z; A_sm[lk + 3][lrow] = av.w;
        B_sm[lk + 0][lrow] = bv.x; B_sm[lk + 1][lrow] = bv.y;
        B_sm[lk + 2][lrow] = bv.z; B_sm[lk + 3][lrow] = bv.w;
        __syncthreads();
#pragma unroll
        for (int kk = 0; kk < 8; ++kk) {
            float a[8];
            *(float4*)(a + 0) = *(const float4*)&A_sm[kk][tm * 8 + 0];
            *(float4*)(a + 4) = *(const float4*)&A_sm[kk][tm * 8 + 4];
            ulonglong2 b01 = *(const ulonglong2*)&B_sm[kk][tn * 8 + 0];
            ulonglong2 b23 = *(const ulonglong2*)&B_sm[kk][tn * 8 + 4];
            ull bb4[4] = {b01.x, b01.y, b23.x, b23.y};
#pragma unroll
            for (int i = 0; i < 8; ++i) {
                const ull ad = pk2(a[i], a[i]);
#pragma unroll
                for (int p = 0; p < 4; ++p) acc[i][p] = ffma2(ad, bb4[p], acc[i][p]);
            }
        }
    }

    float bvals[8];
#pragma unroll
    for (int j = 0; j < 8; ++j) bvals[j] = bias[n0 + tn * 8 + j];
#pragma unroll
    for (int i = 0; i < 8; ++i) {
        float c[8];
#pragma unroll
        for (int p = 0; p < 4; ++p) upk2(acc[i][p], c[2 * p], c[2 * p + 1]);
        const int m = m0 + tm * 8 + i;
        float* orow = (!bwd ? d_xg + (size_t)m * G4n
                            : d_xgb + (size_t)(m - 16384) * G4n) + n0 + tn * 8;
        float4 o0 = make_float4(c[0] + bvals[0], c[1] + bvals[1],
                                c[2] + bvals[2], c[3] + bvals[3]);
        float4 o1 = make_float4(c[4] + bvals[4], c[5] + bvals[5],
                                c[6] + bvals[6], c[7] + bvals[7]);
        *(float4*)(orow + 0) = o0;
        *(float4*)(orow + 4) = o1;
    }
}

// ======================= K2: persistent LSTM recurrence ====================
// 148 launched blocks of 512 threads; first 128 work (4 groups x 32 blocks;
// block owns 16 h-cells). W lives in REGISTERS (64 regs/thread, constant
// across steps) -- the GEMM's only smem operand is h, loaded via broadcast
// LDS.128 (conflict-free). Kills the smem-crossbar bottleneck (L1 was ~50%).
// Warp ks owns k-slice [32ks,32ks+32); lane owns row-pair (2*lane, 2*lane+1)
// and all 8 batches. Partial layout/PhaseB/flags unchanged from R12/R13.
__global__ void __launch_bounds__(512, 1) k_rec(
    const float* __restrict__ Whh, int steps, int dircol)
{
    extern __shared__ float smem[];
    ull*   hdup = (ull*)smem;                           // [512][8]      32 KB
    float* part = (float*)(hdup + 512 * 8);             // [2][16][512]  64 KB

    if (blockIdx.x >= 128) return;   // padding blocks (grid>=148 only)

    const int tid  = threadIdx.x;
    const int g    = blockIdx.x & 3;
    const int rblk = blockIdx.x >> 2;
    const int cbase = rblk * 16;

    const int ks   = tid >> 5;          // warp id 0..15 == K-slice (32 k each)
    const int lane = tid & 31;

    // ---- W into registers: lane holds rows (2*lane, 2*lane+1) x 32 k ----
    // row r = q*16 + j  <-> Whh row q*512 + cbase + j
    ull wreg[32];
    {
        const int q  = lane >> 3;            // (2*lane) >> 4
        const int j0 = (2 * lane) & 15;      // even; j0+1 stays in same q
        const float* wr0 = Whh + (size_t)(q * Hn + cbase + j0) * Hn + ks * 32;
        const float* wr1 = wr0 + Hn;
#pragma unroll
        for (int kk = 0; kk < 32; ++kk)
            wreg[kk] = pk2(__ldg(wr0 + kk), __ldg(wr1 + kk));
    }

    // warp ks consumes cells [32ks, 32ks+32) = producer blocks 2ks, 2ks+1
    const unsigned* myflag = &d_flag[dircol][g][ks * 2 + (lane & 1)].v;

    // PhaseB identity (threads 0..127): cell pb_j of batch pb_b
    const int pb_b = tid >> 4;
    const int pb_j = tid & 15;
    const int bglob = g * 8 + pb_b;

    float c_reg = 0.0f;

    // xg prefetch for t = 0
    float xgi = 0.f, xgf = 0.f, xgg = 0.f, xgo = 0.f;
    if (tid < 128) {
        const int xs0 = dircol ? (steps - 1) : 0;
        const float* xb = (dircol ? d_xgb : d_xg)
                        + (size_t)(xs0 * 32 + bglob) * G4n + cbase + pb_j;
        xgi = __ldg(xb);
        xgf = __ldg(xb + 512);
        xgg = __ldg(xb + 1024);
        xgo = __ldg(xb + 1536);
    }
    __syncthreads();

    for (int t = 0; t < steps; ++t) {
        const int xs = dircol ? (steps - 1 - t) : t;

        // ---- per-warp: wait for own 2 producers, stage own 2KB h slice ----
        if (t == 0) {
#pragma unroll
            for (int i = 0; i < 8; ++i) hdup[ks * 256 + lane + 32 * i] = 0ull;
        } else {
            if (lane < 2) {
                while (ld_acq(myflag) < (unsigned)t) { }
            }
            __syncwarp();
            const uint4* src = (const uint4*)&d_hring[t - 1][g][ks * 32][0];
            uint4* dst = (uint4*)(hdup + ks * 256);
#pragma unroll
            for (int i = 0; i < 4; ++i)
                dst[lane + 32 * i] = __ldcg(src + lane + 32 * i);
        }
        __syncwarp();

        // ---- GEMM: rows (2*lane,2*lane+1) x 8 batches x k-slice 32 ----
        ull acc[8];
#pragma unroll
        for (int b = 0; b < 8; ++b) acc[b] = 0ull;

        const ull* hp = hdup + (ks * 32) * 8;
#pragma unroll 8
        for (int kk = 0; kk < 32; ++kk) {
            ulonglong2 h01 = *(const ulonglong2*)(hp + 0);
            ulonglong2 h23 = *(const ulonglong2*)(hp + 2);
            ulonglong2 h45 = *(const ulonglong2*)(hp + 4);
            ulonglong2 h67 = *(const ulonglong2*)(hp + 6);
            hp += 8;
            const ull w = wreg[kk];
            acc[0] = ffma2(w, h01.x, acc[0]);
            acc[1] = ffma2(w, h01.y, acc[1]);
            acc[2] = ffma2(w, h23.x, acc[2]);
            acc[3] = ffma2(w, h23.y, acc[3]);
            acc[4] = ffma2(w, h45.x, acc[4]);
            acc[5] = ffma2(w, h45.y, acc[5]);
            acc[6] = ffma2(w, h67.x, acc[6]);
            acc[7] = ffma2(w, h67.y, acc[7]);
        }
        float* pbuf = part + (t & 1) * 8192;
#pragma unroll
        for (int b = 0; b < 8; ++b)
            *(ull*)&pbuf[ks * 512 + b * 64 + 2 * lane] = acc[b];
        __syncthreads();   // all 16 partials of step t in pbuf

        // ---- PhaseB (warps 0-3) + publish; warps 4-15 race ahead to t+1 ----
        if (tid < 128) {
            float gi = xgi, gf = xgf, gg = xgg, go = xgo;
#pragma unroll
            for (int p = 0; p < 16; ++p) {
                const float* pp = pbuf + p * 512 + pb_b * 64;
                gi += pp[pb_j];
                gf += pp[16 + pb_j];
                gg += pp[32 + pb_j];
                go += pp[48 + pb_j];
            }
            c_reg = sigf(gf) * c_reg + sigf(gi) * tanhf(gg);
            const float hv = sigf(go) * tanhf(c_reg);
            __stcg(&d_hring[t][g][cbase + pb_j][pb_b], pk2(hv, hv));
            const int srel = dircol ? xs : (t - 496);
            if (srel >= 0)
                d_hsel[((size_t)bglob * 16 + srel) * En + dircol * Hn + cbase + pb_j] = hv;

            // intra-CTA HB edge: weak stores above -> barrier -> release below
            asm volatile("bar.sync 1, 128;" ::: "memory");   // warps 0-3 only
            if (tid == 0) {
                st_rel(&d_flag[dircol][g][rblk].v, (unsigned)(t + 1));
            }
            // prefetch next step's xg (off the critical path)
            if (t + 1 < steps) {
                const int xs1 = dircol ? (steps - 2 - t) : (t + 1);
                const float* xb = (dircol ? d_xgb : d_xg)
                                + (size_t)(xs1 * 32 + bglob) * G4n + cbase + pb_j;
                xgi = __ldg(xb);
                xgf = __ldg(xb + 512);
                xgg = __ldg(xb + 1024);
                xgo = __ldg(xb + 1536);
            }
        }
    }
}

// ======================= K3: weight packing + folds ========================
__global__ void __launch_bounds__(256) k_pack(
    const float* __restrict__ Wk, const float* __restrict__ bk,
    const float* __restrict__ Wv, const float* __restrict__ bv,
    const float* __restrict__ Wq, const float* __restrict__ bq)
{
    const int r = blockIdx.x;
    const float* src = nullptr;
    float bsv = 0.0f;
    if (r < 1024)      { src = Wk + (size_t)r * En;                bsv = bk[r]; }
    else if (r < 2048) { src = Wv + (size_t)(r - 1024) * En;       bsv = bv[r - 1024]; }
    else if (r < 2112) { src = Wq + (size_t)(960 + r - 2048) * En; bsv = bq[960 + r - 2048]; }
    float* dst = d_wpack + (size_t)r * En;
    if (src) {
        for (int i = threadIdx.x * 4; i < En; i += 1024)
            *(float4*)(dst + i) = *(const float4*)(src + i);
    } else {
        const float4 z4 = make_float4(0.f, 0.f, 0.f, 0.f);
        for (int i = threadIdx.x * 4; i < En; i += 1024) *(float4*)(dst + i) = z4;
    }
    if (threadIdx.x == 0) d_bpack[r] = bsv;
}

__global__ void __launch_bounds__(256) k_weff(
    const float* __restrict__ Wfc, const float* __restrict__ Wo,
    const float* __restrict__ bo,  const float* __restrict__ bfc)
{
    const int i = blockIdx.x * 256 + threadIdx.x;   // 0..1023
    float acc = 0.0f;
    for (int e = 0; e < En; ++e) acc += Wfc[e] * Wo[(size_t)e * En + i];
    d_weff[i] = acc;
    if (blockIdx.x == 0) {
        __shared__ float red[256];
        float p = 0.0f;
        for (int e = threadIdx.x; e < En; e += 256) p += Wfc[e] * bo[e];
        red[threadIdx.x] = p; __syncthreads();
        for (int o = 128; o > 0; o >>= 1) {
            if (threadIdx.x < o) red[threadIdx.x] += red[threadIdx.x + o];
            __syncthreads();
        }
        if (threadIdx.x == 0) d_scal0 = red[0] + bfc[0];
    }
}

// ======================= K4: QKV GEMM ======================================
__global__ void __launch_bounds__(256) k_qkv()
{
    __shared__ __align__(16) float A_sm[8][128];
    __shared__ __align__(16) float B_sm[8][128];
    const int tid = threadIdx.x;
    const int m0 = blockIdx.y * 128;
    const int n0 = blockIdx.x * 128;
    const int lrow = tid >> 1;
    const int lk   = (tid & 1) * 4;
    const float* __restrict__ arow = d_hsel + (size_t)(m0 + lrow) * En;
    const float* __restrict__ wrow = d_wpack + (size_t)(n0 + lrow) * En;
    const int tm = tid >> 4;
    const int tn = tid & 15;

    ull acc[8][4];
#pragma unroll
    for (int i = 0; i < 8; ++i)
#pragma unroll
        for (int p = 0; p < 4; ++p) acc[i][p] = 0ull;

    for (int k0 = 0; k0 < En; k0 += 8) {
        float4 av = *(const float4*)(arow + k0 + lk);
        float4 bv = *(const float4*)(wrow + k0 + lk);
        __syncthreads();
        A_sm[lk + 0][lrow] = av.x; A_sm[lk + 1][lrow] = av.y;
        A_sm[lk + 2][lrow] = av.z; A_sm[lk + 3][lrow] = av.w;
        B_sm[lk + 0][lrow] = bv.x; B_sm[lk + 1][lrow] = bv.y;
        B_sm[lk + 2][lrow] = bv.z; B_sm[lk + 3][lrow] = bv.w;
        __syncthreads();
#pragma unroll
        for (int kk = 0; kk < 8; ++kk) {
            float a[8];
            *(float4*)(a + 0) = *(const float4*)&A_sm[kk][tm * 8 + 0];
            *(float4*)(a + 4) = *(const float4*)&A_sm[kk][tm * 8 + 4];
            ulonglong2 b01 = *(const ulonglong2*)&B_sm[kk][tn * 8 + 0];
            ulonglong2 b23 = *(const ulonglong2*)&B_sm[kk][tn * 8 + 4];
            ull bb4[4] = {b01.x, b01.y, b23.x, b23.y};
#pragma unroll
            for (int i = 0; i < 8; ++i) {
                const ull ad = pk2(a[i], a[i]);
#pragma unroll
                for (int p = 0; p < 4; ++p) acc[i][p] = ffma2(ad, bb4[p], acc[i][p]);
            }
        }
    }

    float bvals[8];
#pragma unroll
    for (int j = 0; j < 8; ++j) bvals[j] = d_bpack[n0 + tn * 8 + j];
#pragma unroll
    for (int i = 0; i < 8; ++i) {
        float c[8];
#pragma unroll
        for (int p = 0; p < 4; ++p) upk2(acc[i][p], c[2 * p], c[2 * p + 1]);
        const int m = m0 + tm * 8 + i;
        float* orow = d_att + (size_t)m * NPACK + n0 + tn * 8;
        float4 o0 = make_float4(c[0] + bvals[0], c[1] + bvals[1],
                                c[2] + bvals[2], c[3] + bvals[3]);
        float4 o1 = make_float4(c[4] + bvals[4], c[5] + bvals[5],
                                c[6] + bvals[6], c[7] + bvals[7]);
        *(float4*)(orow + 0) = o0;
        *(float4*)(orow + 4) = o1;
    }
}

// ======================= K5: head-gram softmax + fold ======================
__global__ void __launch_bounds__(512) k_attn(float* __restrict__ out)
{
    __shared__ float sm[16];
    const int b = blockIdx.x;
    const int w = threadIdx.x >> 5;     // srel
    const int lane = threadIdx.x & 31;
    const float* __restrict__ row = d_att + (size_t)(b * 16 + w) * NPACK;

    float sc = 0.0f;
    if (lane < 16) {
        const float4* q4 = (const float4*)(row + 2048);
        const float4* k4 = (const float4*)(row + lane * 64);
#pragma unroll
        for (int i = 0; i < 16; ++i) {
            float4 q = q4[i], k = k4[i];
            sc += q.x * k.x + q.y * k.y + q.z * k.z + q.w * k.w;
        }
        sc *= 0.125f;
    } else sc = -INFINITY;

    float m = sc;
#pragma unroll
    for (int o = 8; o > 0; o >>= 1) m = fmaxf(m, __shfl_xor_sync(0xffffffffu, m, o));
    float e = (lane < 16) ? expf(sc - m) : 0.0f;
    float den = e;
#pragma unroll
    for (int o = 8; o > 0; o >>= 1) den += __shfl_xor_sync(0xffffffffu, den, o);

    float pre0 = 0.0f, pre1 = 0.0f;
#pragma unroll
    for (int kh = 0; kh < 16; ++kh) {
        const float a = __shfl_sync(0xffffffffu, e, kh);
        pre0 += a * row[1024 + kh * 64 + lane];
        pre1 += a * row[1024 + kh * 64 + lane + 32];
    }
    const float dn = __shfl_sync(0xffffffffu, den, 0);
    float acc = (pre0 * d_weff[w * 64 + lane] + pre1 * d_weff[w * 64 + lane + 32]) / dn;
#pragma unroll
    for (int o = 16; o > 0; o >>= 1) acc += __shfl_xor_sync(0xffffffffu, acc, o);
    if (lane == 0) sm[w] = acc;
    __syncthreads();
    if (threadIdx.x == 0) {
        float z = d_scal0;
#pragma unroll
        for (int h = 0; h < 16; ++h) z += sm[h];
        out[b] = 1.0f / (1.0f + expf(-z));
    }
}

// ======================= launch ===========================================
extern "C" void kernel_launch(void* const* d_in, const int* in_sizes, int n_in,
                              void* d_out, int out_size)
{
    const float* x    = (const float*)d_in[0];
    const float* Wihf = (const float*)d_in[1];
    const float* Whhf = (const float*)d_in[2];
    const float* bf   = (const float*)d_in[3];
    const float* Wihb = (const float*)d_in[4];
    const float* Whhb = (const float*)d_in[5];
    const float* bb   = (const float*)d_in[6];
    const float* Wq   = (const float*)d_in[7];
    const float* bq   = (const float*)d_in[8];
    const float* Wk   = (const float*)d_in[9];
    const float* bk   = (const float*)d_in[10];
    const float* Wv   = (const float*)d_in[11];
    const float* bv   = (const float*)d_in[12];
    const float* Wo   = (const float*)d_in[13];
    const float* bo   = (const float*)d_in[14];
    const float* Wfc  = (const float*)d_in[15];
    const float* bfc  = (const float*)d_in[16];
    float* out = (float*)d_out;

    // smem: hdup 32KB + part(double) 64KB = 96KB
    const int rec_smem = 512 * 8 * 8 + 2 * 8192 * 4;
    cudaFuncSetAttribute(k_rec, cudaFuncAttributeMaxDynamicSharedMemorySize, rec_smem);

    k_flagreset<<<1, 256>>>();
    k_xg<<<dim3(16, 132), 256>>>(x, Wihf, bf, Wihb, bb);
    k_rec<<<148, 512, rec_smem>>>(Whhf, 512, 0);
    k_rec<<<148, 512, rec_smem>>>(Whhb, 16, 1);
    k_pack<<<NPACK, 256>>>(Wk, bk, Wv, bv, Wq, bq);
    k_weff<<<4, 256>>>(Wfc, Wo, bo, bfc);
    k_qkv<<<dim3(17, 4), 256>>>();
    k_attn<<<32, 512>>>(out);
}

// round 16
// speedup vs baseline: 1.1794x; 1.1794x over previous
#include <cuda_runtime.h>
#include <math.h>
#include <stdint.h>

// dims
#define Bn   32
#define Sn   512
#define In   256
#define Hn   512
#define G4n  2048
#define En   1024
#define NPACK 2176   // 1024 K-rows + 1024 V-rows + 64 Q15-rows + 64 zero pad
#define NGRP 4       // batch groups (8 batches each), 32 blocks per group

typedef unsigned long long ull;

// ---------------- static device scratch ----------------
__device__ float d_xg [(size_t)Sn * Bn * G4n];   // fwd input gates, row m=s*32+b, col g (128 MB)
__device__ float d_xgb[(size_t)16 * Bn * G4n];   // bwd input gates, row m=srel*32+b
__device__ float d_hringf[Sn][NGRP][Hn][8];      // h per step, NON-dup [k][batch] (33.5 MB)
__device__ float d_hsel[(size_t)Bn * 16 * En];   // h at s in [496,512): [(b*16+srel)][e]
__device__ float d_wpack[(size_t)NPACK * En];
__device__ float d_bpack[NPACK];
__device__ float d_att[(size_t)512 * NPACK];     // per (b,srel): K(1024) V(1024) Q15(64)
__device__ float d_weff[En];
__device__ float d_scal0;

// per-producer flags: one 128B L2 line each. flag = number of completed steps.
struct __align__(128) BarLine { unsigned v; unsigned pad[31]; };
__device__ BarLine d_flag[2][NGRP][32];          // [dircol][group][producer blk]

__device__ __forceinline__ float sigf(float x) { return 1.0f / (1.0f + expf(-x)); }

__device__ __forceinline__ unsigned ld_acq(const unsigned* p) {
    unsigned v;
    asm volatile("ld.acquire.gpu.u32 %0, [%1];" : "=r"(v) : "l"(p) : "memory");
    return v;
}
__device__ __forceinline__ void st_rel(unsigned* p, unsigned v) {
    asm volatile("st.release.gpu.u32 [%0], %1;" :: "l"(p), "r"(v) : "memory");
}

// ---- packed fp32x2 helpers (bit-exact 2x fp32 FMA) ----
__device__ __forceinline__ ull ffma2(ull a, ull b, ull c) {
    ull d;
    asm("fma.rn.f32x2 %0, %1, %2, %3;" : "=l"(d) : "l"(a), "l"(b), "l"(c));
    return d;
}
__device__ __forceinline__ ull pk2(float x, float y) {
    ull r;
    asm("mov.b64 %0, {%1, %2};" : "=l"(r)
        : "r"(__float_as_uint(x)), "r"(__float_as_uint(y)));
    return r;
}
__device__ __forceinline__ void upk2(ull v, float& x, float& y) {
    unsigned lo, hi;
    asm("mov.b64 {%0, %1}, %2;" : "=r"(lo), "=r"(hi) : "l"(v));
    x = __uint_as_float(lo); y = __uint_as_float(hi);
}

// ======================= K0: re-arm flags (each replay) ====================
__global__ void k_flagreset()
{
    BarLine* f = &d_flag[0][0][0];
    f[threadIdx.x].v = 0u;    // 256 = 2*4*32
}

// ======================= K1: xg = x @ W_ih^T + b ===========================
__global__ void __launch_bounds__(256) k_xg(
    const float* __restrict__ x,
    const float* __restrict__ Wihf, const float* __restrict__ bf,
    const float* __restrict__ Wihb, const float* __restrict__ bb)
{
    __shared__ __align__(16) float A_sm[8][128];
    __shared__ __align__(16) float B_sm[8][128];
    const int tid = threadIdx.x;
    const bool bwd = (blockIdx.y >= 128);
    const float* __restrict__ W    = bwd ? Wihb : Wihf;
    const float* __restrict__ bias = bwd ? bb   : bf;
    const int m0 = blockIdx.y * 128;
    const int n0 = blockIdx.x * 128;

    const int lrow = tid >> 1;
    const int lk   = (tid & 1) * 4;
    const int mg = m0 + lrow;
    int sA, bA;
    if (!bwd) { sA = mg >> 5; bA = mg & 31; }
    else { const int ml = mg - 16384; sA = 496 + (ml >> 5); bA = ml & 31; }
    const float* __restrict__ xrow = x + ((size_t)bA * Sn + sA) * In;
    const float* __restrict__ wrow = W + (size_t)(n0 + lrow) * In;

    const int tm = tid >> 4;
    const int tn = tid & 15;

    ull acc[8][4];
#pragma unroll
    for (int i = 0; i < 8; ++i)
#pragma unroll
        for (int p = 0; p < 4; ++p) acc[i][p] = 0ull;

    for (int k0 = 0; k0 < In; k0 += 8) {
        float4 av = *(const float4*)(xrow + k0 + lk);
        float4 bv = *(const float4*)(wrow + k0 + lk);
        __syncthreads();
        A_sm[lk + 0][lrow] = av.x; A_sm[lk + 1][lrow] = av.y;
        A_sm[lk + 2][lrow] = av.z; A_sm[lk + 3][lrow] = av.w;
        B_sm[lk + 0][lrow] = bv.x; B_sm[lk + 1][lrow] = bv.y;
        B_sm[lk + 2][lrow] = bv.z; B_sm[lk + 3][lrow] = bv.w;
        __syncthreads();
#pragma unroll
        for (int kk = 0; kk < 8; ++kk) {
            float a[8];
            *(float4*)(a + 0) = *(const float4*)&A_sm[kk][tm * 8 + 0];
            *(float4*)(a + 4) = *(const float4*)&A_sm[kk][tm * 8 + 4];
            ulonglong2 b01 = *(const ulonglong2*)&B_sm[kk][tn * 8 + 0];
            ulonglong2 b23 = *(const ulonglong2*)&B_sm[kk][tn * 8 + 4];
            ull bb4[4] = {b01.x, b01.y, b23.x, b23.y};
#pragma unroll
            for (int i = 0; i < 8; ++i) {
                const ull ad = pk2(a[i], a[i]);
#pragma unroll
                for (int p = 0; p < 4; ++p) acc[i][p] = ffma2(ad, bb4[p], acc[i][p]);
            }
        }
    }

    float bvals[8];
#pragma unroll
    for (int j = 0; j < 8; ++j) bvals[j] = bias[n0 + tn * 8 + j];
#pragma unroll
    for (int i = 0; i < 8; ++i) {
        float c[8];
#pragma unroll
        for (int p = 0; p < 4; ++p) upk2(acc[i][p], c[2 * p], c[2 * p + 1]);
        const int m = m0 + tm * 8 + i;
        float* orow = (!bwd ? d_xg + (size_t)m * G4n
                            : d_xgb + (size_t)(m - 16384) * G4n) + n0 + tn * 8;
        float4 o0 = make_float4(c[0] + bvals[0], c[1] + bvals[1],
                                c[2] + bvals[2], c[3] + bvals[3]);
        float4 o1 = make_float4(c[4] + bvals[4], c[5] + bvals[5],
                                c[6] + bvals[6], c[7] + bvals[7]);
        *(float4*)(orow + 0) = o0;
        *(float4*)(orow + 4) = o1;
    }
}

// ======================= K2: persistent LSTM recurrence ====================
// 148 launched blocks of 512 threads; first 128 work (4 groups x 32 blocks;
// block owns 16 h-cells). R16: f32x2 packs BATCH pairs; h stored NON-dup
// [k][8b] (2 broadcast LDS.128 per k = 32B per 16 MACs, vs 48B R12 / 64B
// R15); W packed non-dup row-pairs in 32 regs, dup multiplier built with
// 1 upk2 + 2 pk2 per k (ALU pipe, off the LSU). Bit-exact partial order.
__global__ void __launch_bounds__(512, 1) k_rec(
    const float* __restrict__ Whh, int steps, int dircol)
{
    extern __shared__ float smem[];
    float* h_sm = smem;                                 // [512][8]      16 KB
    float* part = smem + 512 * 8;                       // [2][16][512]  64 KB

    if (blockIdx.x >= 128) return;   // padding blocks (grid>=148 only)

    const int tid  = threadIdx.x;
    const int g    = blockIdx.x & 3;
    const int rblk = blockIdx.x >> 2;
    const int cbase = rblk * 16;

    const int ks   = tid >> 5;          // warp id 0..15 == K-slice (32 k each)
    const int lane = tid & 31;

    // ---- W into registers NON-dup: wreg[kk] = (W[row 2l][k], W[row 2l+1][k])
    // row r = q*16 + j  <-> Whh row q*512 + cbase + j
    ull wreg[32];
    {
        const int q  = lane >> 3;            // (2*lane) >> 4
        const int j0 = (2 * lane) & 15;      // even; j0+1 stays in same q
        const float* wr0 = Whh + (size_t)(q * Hn + cbase + j0) * Hn + ks * 32;
        const float* wr1 = wr0 + Hn;
#pragma unroll
        for (int kk = 0; kk < 32; ++kk)
            wreg[kk] = pk2(__ldg(wr0 + kk), __ldg(wr1 + kk));
    }

    // warp ks consumes cells [32ks, 32ks+32) = producer blocks 2ks, 2ks+1
    const unsigned* myflag = &d_flag[dircol][g][ks * 2 + (lane & 1)].v;

    // PhaseB identity (threads 0..127): cell pb_j of batch pb_b
    const int pb_b = tid >> 4;
    const int pb_j = tid & 15;
    const int bglob = g * 8 + pb_b;

    float c_reg = 0.0f;

    // xg prefetch for t = 0
    float xgi = 0.f, xgf = 0.f, xgg = 0.f, xgo = 0.f;
    if (tid < 128) {
        const int xs0 = dircol ? (steps - 1) : 0;
        const float* xb = (dircol ? d_xgb : d_xg)
                        + (size_t)(xs0 * 32 + bglob) * G4n + cbase + pb_j;
        xgi = __ldg(xb);
        xgf = __ldg(xb + 512);
        xgg = __ldg(xb + 1024);
        xgo = __ldg(xb + 1536);
    }
    __syncthreads();

    for (int t = 0; t < steps; ++t) {
        const int xs = dircol ? (steps - 1 - t) : t;

        // ---- per-warp: wait for own 2 producers, stage own 1KB h slice ----
        if (t == 0) {
            const uint4 z4 = make_uint4(0u, 0u, 0u, 0u);
            uint4* dst = (uint4*)(h_sm + ks * 256);
            dst[lane] = z4;
            dst[lane + 32] = z4;
        } else {
            if (lane < 2) {
                while (ld_acq(myflag) < (unsigned)t) { }
            }
            __syncwarp();
            const uint4* src = (const uint4*)&d_hringf[t - 1][g][ks * 32][0];
            uint4* dst = (uint4*)(h_sm + ks * 256);
            dst[lane]      = __ldcg(src + lane);
            dst[lane + 32] = __ldcg(src + lane + 32);
        }
        __syncwarp();

        // ---- GEMM: rows (2l,2l+1) x 8 batches(bpairs) x k-slice 32 ----
        ull acc[2][4];
#pragma unroll
        for (int r = 0; r < 2; ++r)
#pragma unroll
            for (int p = 0; p < 4; ++p) acc[r][p] = 0ull;

        const float* hp = h_sm + (ks * 32) * 8;
#pragma unroll 8
        for (int kk = 0; kk < 32; ++kk) {
            ulonglong2 hA = *(const ulonglong2*)(hp);       // bpairs (0,1),(2,3)
            ulonglong2 hB = *(const ulonglong2*)(hp + 4);   // bpairs (4,5),(6,7)
            hp += 8;
            float w0, w1; upk2(wreg[kk], w0, w1);
            const ull a0 = pk2(w0, w0);
            const ull a1 = pk2(w1, w1);
            acc[0][0] = ffma2(a0, hA.x, acc[0][0]);
            acc[0][1] = ffma2(a0, hA.y, acc[0][1]);
            acc[0][2] = ffma2(a0, hB.x, acc[0][2]);
            acc[0][3] = ffma2(a0, hB.y, acc[0][3]);
            acc[1][0] = ffma2(a1, hA.x, acc[1][0]);
            acc[1][1] = ffma2(a1, hA.y, acc[1][1]);
            acc[1][2] = ffma2(a1, hB.x, acc[1][2]);
            acc[1][3] = ffma2(a1, hB.y, acc[1][3]);
        }
        // store partials in [w][b][64-row] layout (PhaseB identical to R12)
        float* pbuf = part + (t & 1) * 8192;
#pragma unroll
        for (int r = 0; r < 2; ++r)
#pragma unroll
            for (int p = 0; p < 4; ++p) {
                float x, y; upk2(acc[r][p], x, y);
                pbuf[ks * 512 + (2 * p) * 64     + 2 * lane + r] = x;
                pbuf[ks * 512 + (2 * p + 1) * 64 + 2 * lane + r] = y;
            }
        __syncthreads();   // all 16 partials of step t in pbuf

        // ---- PhaseB (warps 0-3) + publish; warps 4-15 race ahead to t+1 ----
        if (tid < 128) {
            float gi = xgi, gf = xgf, gg = xgg, go = xgo;
#pragma unroll
            for (int p = 0; p < 16; ++p) {
                const float* pp = pbuf + p * 512 + pb_b * 64;
                gi += pp[pb_j];
                gf += pp[16 + pb_j];
                gg += pp[32 + pb_j];
                go += pp[48 + pb_j];
            }
            c_reg = sigf(gf) * c_reg + sigf(gi) * tanhf(gg);
            const float hv = sigf(go) * tanhf(c_reg);
            __stcg(&d_hringf[t][g][cbase + pb_j][pb_b], hv);
            const int srel = dircol ? xs : (t - 496);
            if (srel >= 0)
                d_hsel[((size_t)bglob * 16 + srel) * En + dircol * Hn + cbase + pb_j] = hv;

            // intra-CTA HB edge: weak stores above -> barrier -> release below
            asm volatile("bar.sync 1, 128;" ::: "memory");   // warps 0-3 only
            if (tid == 0) {
                st_rel(&d_flag[dircol][g][rblk].v, (unsigned)(t + 1));
            }
            // prefetch next step's xg (off the critical path)
            if (t + 1 < steps) {
                const int xs1 = dircol ? (steps - 2 - t) : (t + 1);
                const float* xb = (dircol ? d_xgb : d_xg)
                                + (size_t)(xs1 * 32 + bglob) * G4n + cbase + pb_j;
                xgi = __ldg(xb);
                xgf = __ldg(xb + 512);
                xgg = __ldg(xb + 1024);
                xgo = __ldg(xb + 1536);
            }
        }
    }
}

// ======================= K3: weight packing + folds ========================
__global__ void __launch_bounds__(256) k_pack(
    const float* __restrict__ Wk, const float* __restrict__ bk,
    const float* __restrict__ Wv, const float* __restrict__ bv,
    const float* __restrict__ Wq, const float* __restrict__ bq)
{
    const int r = blockIdx.x;
    const float* src = nullptr;
    float bsv = 0.0f;
    if (r < 1024)      { src = Wk + (size_t)r * En;                bsv = bk[r]; }
    else if (r < 2048) { src = Wv + (size_t)(r - 1024) * En;       bsv = bv[r - 1024]; }
    else if (r < 2112) { src = Wq + (size_t)(960 + r - 2048) * En; bsv = bq[960 + r - 2048]; }
    float* dst = d_wpack + (size_t)r * En;
    if (src) {
        for (int i = threadIdx.x * 4; i < En; i += 1024)
            *(float4*)(dst + i) = *(const float4*)(src + i);
    } else {
        const float4 z4 = make_float4(0.f, 0.f, 0.f, 0.f);
        for (int i = threadIdx.x * 4; i < En; i += 1024) *(float4*)(dst + i) = z4;
    }
    if (threadIdx.x == 0) d_bpack[r] = bsv;
}

__global__ void __launch_bounds__(256) k_weff(
    const float* __restrict__ Wfc, const float* __restrict__ Wo,
    const float* __restrict__ bo,  const float* __restrict__ bfc)
{
    const int i = blockIdx.x * 256 + threadIdx.x;   // 0..1023
    float acc = 0.0f;
    for (int e = 0; e < En; ++e) acc += Wfc[e] * Wo[(size_t)e * En + i];
    d_weff[i] = acc;
    if (blockIdx.x == 0) {
        __shared__ float red[256];
        float p = 0.0f;
        for (int e = threadIdx.x; e < En; e += 256) p += Wfc[e] * bo[e];
        red[threadIdx.x] = p; __syncthreads();
        for (int o = 128; o > 0; o >>= 1) {
            if (threadIdx.x < o) red[threadIdx.x] += red[threadIdx.x + o];
            __syncthreads();
        }
        if (threadIdx.x == 0) d_scal0 = red[0] + bfc[0];
    }
}

// ======================= K4: QKV GEMM ======================================
__global__ void __launch_bounds__(256) k_qkv()
{
    __shared__ __align__(16) float A_sm[8][128];
    __shared__ __align__(16) float B_sm[8][128];
    const int tid = threadIdx.x;
    const int m0 = blockIdx.y * 128;
    const int n0 = blockIdx.x * 128;
    const int lrow = tid >> 1;
    const int lk   = (tid & 1) * 4;
    const float* __restrict__ arow = d_hsel + (size_t)(m0 + lrow) * En;
    const float* __restrict__ wrow = d_wpack + (size_t)(n0 + lrow) * En;
    const int tm = tid >> 4;
    const int tn = tid & 15;

    ull acc[8][4];
#pragma unroll
    for (int i = 0; i < 8; ++i)
#pragma unroll
        for (int p = 0; p < 4; ++p) acc[i][p] = 0ull;

    for (int k0 = 0; k0 < En; k0 += 8) {
        float4 av = *(const float4*)(arow + k0 + lk);
        float4 bv = *(const float4*)(wrow + k0 + lk);
        __syncthreads();
        A_sm[lk + 0][lrow] = av.x; A_sm[lk + 1][lrow] = av.y;
        A_sm[lk + 2][lrow] = av.z; A_sm[lk + 3][lrow] = av.w;
        B_sm[lk + 0][lrow] = bv.x; B_sm[lk + 1][lrow] = bv.y;
        B_sm[lk + 2][lrow] = bv.z; B_sm[lk + 3][lrow] = bv.w;
        __syncthreads();
#pragma unroll
        for (int kk = 0; kk < 8; ++kk) {
            float a[8];
            *(float4*)(a + 0) = *(const float4*)&A_sm[kk][tm * 8 + 0];
            *(float4*)(a + 4) = *(const float4*)&A_sm[kk][tm * 8 + 4];
            ulonglong2 b01 = *(const ulonglong2*)&B_sm[kk][tn * 8 + 0];
            ulonglong2 b23 = *(const ulonglong2*)&B_sm[kk][tn * 8 + 4];
            ull bb4[4] = {b01.x, b01.y, b23.x, b23.y};
#pragma unroll
            for (int i = 0; i < 8; ++i) {
                const ull ad = pk2(a[i], a[i]);
#pragma unroll
                for (int p = 0; p < 4; ++p) acc[i][p] = ffma2(ad, bb4[p], acc[i][p]);
            }
        }
    }

    float bvals[8];
#pragma unroll
    for (int j = 0; j < 8; ++j) bvals[j] = d_bpack[n0 + tn * 8 + j];
#pragma unroll
    for (int i = 0; i < 8; ++i) {
        float c[8];
#pragma unroll
        for (int p = 0; p < 4; ++p) upk2(acc[i][p], c[2 * p], c[2 * p + 1]);
        const int m = m0 + tm * 8 + i;
        float* orow = d_att + (size_t)m * NPACK + n0 + tn * 8;
        float4 o0 = make_float4(c[0] + bvals[0], c[1] + bvals[1],
                                c[2] + bvals[2], c[3] + bvals[3]);
        float4 o1 = make_float4(c[4] + bvals[4], c[5] + bvals[5],
                                c[6] + bvals[6], c[7] + bvals[7]);
        *(float4*)(orow + 0) = o0;
        *(float4*)(orow + 4) = o1;
    }
}

// ======================= K5: head-gram softmax + fold ======================
__global__ void __launch_bounds__(512) k_attn(float* __restrict__ out)
{
    __shared__ float sm[16];
    const int b = blockIdx.x;
    const int w = threadIdx.x >> 5;     // srel
    const int lane = threadIdx.x & 31;
    const float* __restrict__ row = d_att + (size_t)(b * 16 + w) * NPACK;

    float sc = 0.0f;
    if (lane < 16) {
        const float4* q4 = (const float4*)(row + 2048);
        const float4* k4 = (const float4*)(row + lane * 64);
#pragma unroll
        for (int i = 0; i < 16; ++i) {
            float4 q = q4[i], k = k4[i];
            sc += q.x * k.x + q.y * k.y + q.z * k.z + q.w * k.w;
        }
        sc *= 0.125f;
    } else sc = -INFINITY;

    float m = sc;
#pragma unroll
    for (int o = 8; o > 0; o >>= 1) m = fmaxf(m, __shfl_xor_sync(0xffffffffu, m, o));
    float e = (lane < 16) ? expf(sc - m) : 0.0f;
    float den = e;
#pragma unroll
    for (int o = 8; o > 0; o >>= 1) den += __shfl_xor_sync(0xffffffffu, den, o);

    float pre0 = 0.0f, pre1 = 0.0f;
#pragma unroll
    for (int kh = 0; kh < 16; ++kh) {
        const float a = __shfl_sync(0xffffffffu, e, kh);
        pre0 += a * row[1024 + kh * 64 + lane];
        pre1 += a * row[1024 + kh * 64 + lane + 32];
    }
    const float dn = __shfl_sync(0xffffffffu, den, 0);
    float acc = (pre0 * d_weff[w * 64 + lane] + pre1 * d_weff[w * 64 + lane + 32]) / dn;
#pragma unroll
    for (int o = 16; o > 0; o >>= 1) acc += __shfl_xor_sync(0xffffffffu, acc, o);
    if (lane == 0) sm[w] = acc;
    __syncthreads();
    if (threadIdx.x == 0) {
        float z = d_scal0;
#pragma unroll
        for (int h = 0; h < 16; ++h) z += sm[h];
        out[b] = 1.0f / (1.0f + expf(-z));
    }
}

// ======================= launch ===========================================
extern "C" void kernel_launch(void* const* d_in, const int* in_sizes, int n_in,
                              void* d_out, int out_size)
{
    const float* x    = (const float*)d_in[0];
    const float* Wihf = (const float*)d_in[1];
    const float* Whhf = (const float*)d_in[2];
    const float* bf   = (const float*)d_in[3];
    const float* Wihb = (const float*)d_in[4];
    const float* Whhb = (const float*)d_in[5];
    const float* bb   = (const float*)d_in[6];
    const float* Wq   = (const float*)d_in[7];
    const float* bq   = (const float*)d_in[8];
    const float* Wk   = (const float*)d_in[9];
    const float* bk   = (const float*)d_in[10];
    const float* Wv   = (const float*)d_in[11];
    const float* bv   = (const float*)d_in[12];
    const float* Wo   = (const float*)d_in[13];
    const float* bo   = (const float*)d_in[14];
    const float* Wfc  = (const float*)d_in[15];
    const float* bfc  = (const float*)d_in[16];
    float* out = (float*)d_out;

    // smem: h_sm 16KB + part(double) 64KB = 80KB
    const int rec_smem = 512 * 8 * 4 + 2 * 8192 * 4;
    cudaFuncSetAttribute(k_rec, cudaFuncAttributeMaxDynamicSharedMemorySize, rec_smem);

    k_flagreset<<<1, 256>>>();
    k_xg<<<dim3(16, 132), 256>>>(x, Wihf, bf, Wihb, bb);
    k_rec<<<148, 512, rec_smem>>>(Whhf, 512, 0);
    k_rec<<<148, 512, rec_smem>>>(Whhb, 16, 1);
    k_pack<<<NPACK, 256>>>(Wk, bk, Wv, bv, Wq, bq);
    k_weff<<<4, 256>>>(Wfc, Wo, bo, bfc);
    k_qkv<<<dim3(17, 4), 256>>>();
    k_attn<<<32, 512>>>(out);
}